// round 3
// baseline (speedup 1.0000x reference)
#include <cuda_runtime.h>
#include <math.h>

typedef unsigned long long ull;

#define Bz 64
#define Hh 1024
#define NNv 65536
#define Mv 64
#define Rv 4
#define SIMBLK (NNv/64)   /* 1024 sim blocks */
#define CSPBLK 64         /* write-head csp blocks per b (1024 n each) */
#define ECHUNK 256        /* fused read chunks */
#define EK (NNv/ECHUNK)   /* 256 n per chunk */
#define ESUB (EK/64)      /* 4 sub-tiles of 64 n */

// ---------------- scratch (device globals: no allocation allowed) ----------
__device__ float g_E[(size_t)Bz*NNv];            // exp(beta*sim) [B,N]
__device__ float g_wpow_w[(size_t)Bz*NNv];       // write-head w_pow
__device__ float g_m1[(size_t)NNv*Mv];           // updated memory
__device__ float g_kn[Bz*Mv];
__device__ float g_ev[Bz*Mv];
__device__ float g_av[Bz*Mv];
__device__ float g_beta[Bz];
__device__ float g_gate[Bz];
__device__ float g_gamma[Bz];
__device__ float g_shift[Bz*3];
__device__ float g_psum[(size_t)Bz*SIMBLK];
__device__ float g_sumexp[Bz];
__device__ float g_tpart[Bz*CSPBLK];             // write-head pow partials
__device__ float g_tpartR[Rv*ECHUNK];            // read-head pow partials
__device__ float g_totals[1+Rv];                 // [0]=write, [1..4]=read totals
__device__ float g_epart[(size_t)Rv*ECHUNK*Bz*Mv]; // fused split-K partials

__device__ __forceinline__ float clip01(float x){ return fminf(fmaxf(x, 0.f), 1.f); }
// fast x^g for x > 0 (x==0 -> -inf -> 0, also fine)
__device__ __forceinline__ float fpow(float x, float g){ return __expf(g * __logf(x)); }

__device__ __forceinline__ ull ffma2(ull a, ull b, ull c){
    ull d;
    asm("fma.rn.f32x2 %0, %1, %2, %3;" : "=l"(d) : "l"(a), "l"(b), "l"(c));
    return d;
}
__device__ __forceinline__ ull dup2(float x){
    ull d;
    asm("mov.b64 %0, {%1, %1};" : "=l"(d) : "f"(x));
    return d;
}
__device__ __forceinline__ void unpack2(ull v, float& lo, float& hi){
    asm("mov.b64 {%0, %1}, %2;" : "=f"(lo), "=f"(hi) : "l"(v));
}

// ---------------- kernel 1: head projections (once per step) ---------------
__global__ void heads_kernel(const float* __restrict__ h,
    const float* __restrict__ key_w,   const float* __restrict__ key_b,
    const float* __restrict__ beta_w,  const float* __restrict__ beta_b,
    const float* __restrict__ gate_w,  const float* __restrict__ gate_b,
    const float* __restrict__ shift_w, const float* __restrict__ shift_b,
    const float* __restrict__ gamma_w, const float* __restrict__ gamma_b,
    const float* __restrict__ erase_w, const float* __restrict__ erase_b,
    const float* __restrict__ add_w,   const float* __restrict__ add_b)
{
    __shared__ float hs[Hh];
    __shared__ float ksh[Mv];
    __shared__ float sdot[6];
    __shared__ float sinv;
    const int b = blockIdx.x, t = threadIdx.x;
    for (int i = t; i < Hh; i += 256) hs[i] = h[(size_t)b*Hh + i];
    __syncthreads();

    if (t < 64) {
        float a0=0,a1=0,a2=0,a3=0;
        for (int j = 0; j < Hh; j += 4) {
            a0 = fmaf(hs[j  ], key_w[(j  )*Mv + t], a0);
            a1 = fmaf(hs[j+1], key_w[(j+1)*Mv + t], a1);
            a2 = fmaf(hs[j+2], key_w[(j+2)*Mv + t], a2);
            a3 = fmaf(hs[j+3], key_w[(j+3)*Mv + t], a3);
        }
        ksh[t] = clip01(a0+a1+a2+a3 + key_b[t]);
    } else if (t < 128) {
        const int m = t - 64;
        float a0=0,a1=0,a2=0,a3=0;
        for (int j = 0; j < Hh; j += 4) {
            a0 = fmaf(hs[j  ], erase_w[(j  )*Mv + m], a0);
            a1 = fmaf(hs[j+1], erase_w[(j+1)*Mv + m], a1);
            a2 = fmaf(hs[j+2], erase_w[(j+2)*Mv + m], a2);
            a3 = fmaf(hs[j+3], erase_w[(j+3)*Mv + m], a3);
        }
        g_ev[b*Mv + m] = clip01(a0+a1+a2+a3 + erase_b[m]);
    } else if (t < 192) {
        const int m = t - 128;
        float a0=0,a1=0,a2=0,a3=0;
        for (int j = 0; j < Hh; j += 4) {
            a0 = fmaf(hs[j  ], add_w[(j  )*Mv + m], a0);
            a1 = fmaf(hs[j+1], add_w[(j+1)*Mv + m], a1);
            a2 = fmaf(hs[j+2], add_w[(j+2)*Mv + m], a2);
            a3 = fmaf(hs[j+3], add_w[(j+3)*Mv + m], a3);
        }
        g_av[b*Mv + m] = clip01(a0+a1+a2+a3 + add_b[m]);
    } else if (t < 198) {
        const int d = t - 192;
        const float* w; int str, col;
        if      (d == 0) { w = beta_w;  str = 1; col = 0; }
        else if (d == 1) { w = gate_w;  str = 1; col = 0; }
        else if (d == 2) { w = gamma_w; str = 1; col = 0; }
        else             { w = shift_w; str = 3; col = d - 3; }
        float a0=0,a1=0;
        for (int j = 0; j < Hh; j += 2) {
            a0 = fmaf(hs[j  ], w[(j  )*str + col], a0);
            a1 = fmaf(hs[j+1], w[(j+1)*str + col], a1);
        }
        sdot[d] = a0 + a1;
    }
    __syncthreads();

    if (t < 32) {
        float v = ksh[t]*ksh[t] + ksh[t+32]*ksh[t+32];
        #pragma unroll
        for (int off = 16; off; off >>= 1) v += __shfl_xor_sync(0xffffffffu, v, off);
        if (t == 0) sinv = 1.f / (sqrtf(v) + 1e-8f);
    }
    __syncthreads();
    if (t < 64) g_kn[b*Mv + t] = ksh[t] * sinv;
    if (t == 0) {
        g_beta[b]  = fmaxf(sdot[0] + beta_b[0], 0.f);
        g_gate[b]  = clip01(sdot[1] + gate_b[0]);
        g_gamma[b] = 1.f + fmaxf(sdot[2] + gamma_b[0], 0.f);
        float x0 = sdot[3] + shift_b[0];
        float x1 = sdot[4] + shift_b[1];
        float x2 = sdot[5] + shift_b[2];
        float mx = fmaxf(x0, fmaxf(x1, x2));
        float e0 = expf(x0-mx), e1 = expf(x1-mx), e2 = expf(x2-mx);
        float is = 1.f / (e0+e1+e2);
        g_shift[b*3+0] = e0*is; g_shift[b*3+1] = e1*is; g_shift[b*3+2] = e2*is;
    }
}

// ------- kernel 2: E[b,n] = exp(beta[b] * (kn[b]·m[n]) / (||m[n]||+eps)) ---
__global__ void sim_kernel(const float* __restrict__ mem,
                           const int* __restrict__ bank, int use_m1)
{
    const float* __restrict__ src = use_m1 ? g_m1
                                           : (mem + (size_t)bank[0]*NNv*Mv);
    __shared__ float knT[64*68];   // [k][b], padded; b contiguous -> natural pairs
    __shared__ float mt [64*68];   // [k][n], padded
    __shared__ float invn[64];
    __shared__ float sbeta[64];
    const int t = threadIdx.x;
    const int n0 = blockIdx.x * 64;

    for (int i = t; i < 64*64; i += 256) {
        int bb = i >> 6, mm = i & 63;
        knT[mm*68 + bb] = g_kn[i];
    }
    for (int i = t; i < 64*64; i += 256) {
        int rr = i >> 6, cc = i & 63;
        mt[cc*68 + rr] = src[(size_t)(n0 + rr)*Mv + cc];
    }
    if (t < 64) sbeta[t] = g_beta[t];
    __syncthreads();
    if (t < 64) {
        float s = 0.f;
        #pragma unroll 16
        for (int k = 0; k < 64; k++) { float v = mt[k*68 + t]; s = fmaf(v, v, s); }
        invn[t] = 1.f / (sqrtf(s) + 1e-8f);
    }
    __syncthreads();

    const int by = t >> 5, nx = t & 31;   // 8 b's (4 pairs), 2 n's per thread
    ull acc[4][2];
    #pragma unroll
    for (int p = 0; p < 4; p++) { acc[p][0] = 0ull; acc[p][1] = 0ull; }

    #pragma unroll 8
    for (int k = 0; k < 64; k++) {
        const ulonglong2 A0 = *(const ulonglong2*)&knT[k*68 + 8*by];
        const ulonglong2 A1 = *(const ulonglong2*)&knT[k*68 + 8*by + 4];
        const float2 Bv = *(const float2*)&mt [k*68 + 2*nx];
        const ull d0 = dup2(Bv.x), d1 = dup2(Bv.y);
        acc[0][0] = ffma2(A0.x, d0, acc[0][0]); acc[0][1] = ffma2(A0.x, d1, acc[0][1]);
        acc[1][0] = ffma2(A0.y, d0, acc[1][0]); acc[1][1] = ffma2(A0.y, d1, acc[1][1]);
        acc[2][0] = ffma2(A1.x, d0, acc[2][0]); acc[2][1] = ffma2(A1.x, d1, acc[2][1]);
        acc[3][0] = ffma2(A1.y, d0, acc[3][0]); acc[3][1] = ffma2(A1.y, d1, acc[3][1]);
    }

    const float2 iv = *(const float2*)&invn[2*nx];
    float ps[8];
    #pragma unroll
    for (int p = 0; p < 4; p++) {
        float c0l, c0h, c1l, c1h;
        unpack2(acc[p][0], c0l, c0h);
        unpack2(acc[p][1], c1l, c1h);
        const int bbl = 8*by + 2*p, bbh = bbl + 1;
        const float btl = sbeta[bbl], bth = sbeta[bbh];
        float e0l = __expf(btl * c0l * iv.x);
        float e1l = __expf(btl * c1l * iv.y);
        float e0h = __expf(bth * c0h * iv.x);
        float e1h = __expf(bth * c1h * iv.y);
        *(float2*)&g_E[(size_t)bbl*NNv + n0 + 2*nx] = make_float2(e0l, e1l);
        *(float2*)&g_E[(size_t)bbh*NNv + n0 + 2*nx] = make_float2(e0h, e1h);
        ps[2*p]   = e0l + e1l;
        ps[2*p+1] = e0h + e1h;
    }
    #pragma unroll
    for (int bi = 0; bi < 8; bi++)
        #pragma unroll
        for (int off = 16; off; off >>= 1)
            ps[bi] += __shfl_xor_sync(0xffffffffu, ps[bi], off);
    if (nx == 0) {
        #pragma unroll
        for (int bi = 0; bi < 8; bi++)
            g_psum[(size_t)(8*by + bi)*SIMBLK + blockIdx.x] = ps[bi];
    }
}

// ---------------- deterministic reductions ---------------------------------
__global__ void reduce_sumexp_kernel()
{
    const int b = blockIdx.x, t = threadIdx.x;
    float s = 0.f;
    for (int i = t; i < SIMBLK; i += 256) s += g_psum[(size_t)b*SIMBLK + i];
    __shared__ float red[256];
    red[t] = s; __syncthreads();
    for (int off = 128; off; off >>= 1) { if (t < off) red[t] += red[t+off]; __syncthreads(); }
    if (t == 0) g_sumexp[b] = red[0];
}

__global__ void reduce_totalW_kernel()
{
    const int t = threadIdx.x;
    float s = 0.f;
    for (int i = t; i < Bz*CSPBLK; i += 256) s += g_tpart[i];
    __shared__ float red[256];
    red[t] = s; __syncthreads();
    for (int off = 128; off; off >>= 1) { if (t < off) red[t] += red[t+off]; __syncthreads(); }
    if (t == 0) g_totals[0] = red[0];
}

__global__ void reduce_totalR_kernel()
{
    const int r = blockIdx.x, t = threadIdx.x;  // ECHUNK==256 threads
    __shared__ float red[256];
    red[t] = g_tpartR[r*ECHUNK + t]; __syncthreads();
    for (int off = 128; off; off >>= 1) { if (t < off) red[t] += red[t+off]; __syncthreads(); }
    if (t == 0) g_totals[1 + r] = red[0];
}

// ----- kernel 3: WRITE head: gate + 3-tap shift + fast pow + partial sum ---
__global__ void csp_write_kernel(const float* __restrict__ ww)
{
    const int b  = blockIdx.y;
    const int c0 = blockIdx.x * 1024;
    const float* __restrict__ wp = ww + (size_t)b*NNv;
    float* __restrict__ wo = g_wpow_w + (size_t)b*NNv;
    const float* __restrict__ Eb = g_E + (size_t)b*NNv;

    __shared__ float wg[1026];
    __shared__ float red[256];
    const float gg   = g_gate[b];
    const float invS = 1.f / g_sumexp[b];
    const float s0 = g_shift[b*3+0], s1 = g_shift[b*3+1], s2 = g_shift[b*3+2];
    const float gm = g_gamma[b];
    const int t = threadIdx.x;

    for (int i = t; i < 1026; i += 256) {
        const int n = c0 + i - 1;
        float v = 0.f;
        if (n >= 0 && n < NNv)
            v = gg * Eb[n] * invS + (1.f - gg) * wp[n];
        wg[i] = v;
    }
    __syncthreads();

    float ls = 0.f;
    #pragma unroll
    for (int j = 0; j < 4; j++) {
        const int i = t + j*256;
        const float wt = fmaf(s0, wg[i], fmaf(s1, wg[i+1], s2*wg[i+2]));
        const float pw = fpow(wt, gm);
        wo[c0 + i] = pw;
        ls += pw;
    }
    red[t] = ls; __syncthreads();
    for (int off = 128; off; off >>= 1) { if (t < off) red[t] += red[t+off]; __syncthreads(); }
    if (t == 0) g_tpart[b*CSPBLK + blockIdx.x] = red[0];
}

// --- kernel 4: m1 = m0*(1 - W^T e) + W^T a   (W = wpow_w * inv_total) ------
// dynamic smem: wsh[64*64] | esD[64*128] | asD[64*128]  (dup'd for FFMA2)
__global__ void memupdate_kernel(const float* __restrict__ mem,
                                 const int* __restrict__ bank)
{
    extern __shared__ float sm[];
    float* wsh = sm;            // [k=b][n], n contiguous -> natural pairs
    float* esD = sm + 4096;     // [b][2m] duplicated
    float* asD = sm + 4096 + 8192;
    const int t = threadIdx.x;
    const int n0 = blockIdx.x * 64;
    const float inv = 1.f / (g_totals[0] + 1e-5f);
    const float* __restrict__ m0 = mem + (size_t)bank[0]*NNv*Mv;

    for (int i = t; i < 64*64; i += 256) {
        int bb = i >> 6, nl = i & 63;
        wsh[i] = g_wpow_w[(size_t)bb*NNv + n0 + nl];
        float ev = g_ev[i]*inv, av = g_av[i]*inv;
        *(float2*)&esD[bb*128 + 2*nl] = make_float2(ev, ev);
        *(float2*)&asD[bb*128 + 2*nl] = make_float2(av, av);
    }
    __syncthreads();

    const int tn = t >> 4, tm = t & 15;   // 4 n (2 pairs) x 4 m per thread
    ull ce[2][4], ca[2][4];
    #pragma unroll
    for (int p = 0; p < 2; p++)
        #pragma unroll
        for (int j = 0; j < 4; j++) { ce[p][j] = 0ull; ca[p][j] = 0ull; }

    #pragma unroll 8
    for (int k = 0; k < 64; k++) {
        const ulonglong2 A  = *(const ulonglong2*)&wsh[k*64  + 4*tn];
        const ulonglong2 E0 = *(const ulonglong2*)&esD[k*128 + 8*tm];
        const ulonglong2 E1 = *(const ulonglong2*)&esD[k*128 + 8*tm + 4];
        const ulonglong2 D0 = *(const ulonglong2*)&asD[k*128 + 8*tm];
        const ulonglong2 D1 = *(const ulonglong2*)&asD[k*128 + 8*tm + 4];
        ce[0][0]=ffma2(A.x,E0.x,ce[0][0]); ce[0][1]=ffma2(A.x,E0.y,ce[0][1]);
        ce[0][2]=ffma2(A.x,E1.x,ce[0][2]); ce[0][3]=ffma2(A.x,E1.y,ce[0][3]);
        ce[1][0]=ffma2(A.y,E0.x,ce[1][0]); ce[1][1]=ffma2(A.y,E0.y,ce[1][1]);
        ce[1][2]=ffma2(A.y,E1.x,ce[1][2]); ce[1][3]=ffma2(A.y,E1.y,ce[1][3]);
        ca[0][0]=ffma2(A.x,D0.x,ca[0][0]); ca[0][1]=ffma2(A.x,D0.y,ca[0][1]);
        ca[0][2]=ffma2(A.x,D1.x,ca[0][2]); ca[0][3]=ffma2(A.x,D1.y,ca[0][3]);
        ca[1][0]=ffma2(A.y,D0.x,ca[1][0]); ca[1][1]=ffma2(A.y,D0.y,ca[1][1]);
        ca[1][2]=ffma2(A.y,D1.x,ca[1][2]); ca[1][3]=ffma2(A.y,D1.y,ca[1][3]);
    }

    #pragma unroll
    for (int p = 0; p < 2; p++) {
        float cel[4], ceh[4], cal[4], cah[4];
        #pragma unroll
        for (int j = 0; j < 4; j++) {
            unpack2(ce[p][j], cel[j], ceh[j]);
            unpack2(ca[p][j], cal[j], cah[j]);
        }
        // even n of the pair
        {
            const size_t n = (size_t)(n0 + 4*tn + 2*p);
            const float4 o = *(const float4*)&m0[n*Mv + 4*tm];
            float4 v;
            v.x = o.x*(1.f - cel[0]) + cal[0];
            v.y = o.y*(1.f - cel[1]) + cal[1];
            v.z = o.z*(1.f - cel[2]) + cal[2];
            v.w = o.w*(1.f - cel[3]) + cal[3];
            *(float4*)&g_m1[n*Mv + 4*tm] = v;
        }
        // odd n of the pair
        {
            const size_t n = (size_t)(n0 + 4*tn + 2*p + 1);
            const float4 o = *(const float4*)&m0[n*Mv + 4*tm];
            float4 v;
            v.x = o.x*(1.f - ceh[0]) + cah[0];
            v.y = o.y*(1.f - ceh[1]) + cah[1];
            v.z = o.z*(1.f - ceh[2]) + cah[2];
            v.w = o.w*(1.f - ceh[3]) + cah[3];
            *(float4*)&g_m1[n*Mv + 4*tm] = v;
        }
    }
}

// ----- kernel 5 (FUSED): read-head gate+shift+pow computed per tile, ------
// fed straight into the split-K einsum. No wpow_r round-trip to HBM.
// dynamic smem: bshD[64*128] | wpT[64*68] | wgs[64*67] | prm[384] | red[256]
__global__ void fused_read_kernel(const float* __restrict__ wr)
{
    extern __shared__ float sm[];
    float* bshD = sm;                       // [k=n][2m] m1 tile duplicated
    float* wpT  = sm + 8192;                // [nl][b] pow tile (b contiguous)
    float* wgs  = sm + 8192 + 4352;         // [b][66] stride 67 (conflict-free)
    float* prm  = sm + 8192 + 4352 + 4288;  // g | invS | gm | s0 | s1 | s2
    float* red  = prm + 384;

    const int chunk = blockIdx.x, r = blockIdx.y;
    const int n0 = chunk * EK;
    const int t = threadIdx.x;

    if (t < 64) {
        prm[t]       = g_gate[t];
        prm[64 + t]  = 1.f / g_sumexp[t];
        prm[128 + t] = g_gamma[t];
        prm[192 + t] = g_shift[t*3+0];
        prm[256 + t] = g_shift[t*3+1];
        prm[320 + t] = g_shift[t*3+2];
    }
    const int tb = t >> 4, tm = t & 15;   // 4 b (2 pairs) x 4 m per thread
    ull acc[2][4];
    #pragma unroll
    for (int p = 0; p < 2; p++)
        #pragma unroll
        for (int j = 0; j < 4; j++) acc[p][j] = 0ull;
    float psum = 0.f;
    __syncthreads();

    for (int sub = 0; sub < ESUB; sub++) {
        const int nb = n0 + sub*64;
        // stage wg with 1-element halo each side
        for (int i = t; i < 64*66; i += 256) {
            const int bb = i / 66, x = i - bb*66;
            const int n = nb - 1 + x;
            float v = 0.f;
            if (n >= 0 && n < NNv) {
                const float gg = prm[bb];
                v = gg * g_E[(size_t)bb*NNv + n] * prm[64 + bb]
                  + (1.f - gg) * wr[((size_t)r*Bz + bb)*NNv + n];
            }
            wgs[bb*67 + x] = v;
        }
        // stage duplicated m1 tile
        for (int i = t; i < 64*64; i += 256) {
            const int kk = i >> 6, mm = i & 63;
            const float v = g_m1[(size_t)(nb + kk)*Mv + mm];
            *(float2*)&bshD[kk*128 + 2*mm] = make_float2(v, v);
        }
        __syncthreads();
        // shift + fast pow -> transposed tile, accumulate pow sum
        for (int i = t; i < 64*64; i += 256) {
            const int nl = i >> 6, bb = i & 63;
            const float* w = &wgs[bb*67 + nl];
            const float wt = fmaf(prm[192+bb], w[0],
                             fmaf(prm[256+bb], w[1], prm[320+bb]*w[2]));
            const float pw = fpow(wt, prm[128 + bb]);
            wpT[nl*68 + bb] = pw;
            psum += pw;
        }
        __syncthreads();
        // GEMM over this 64-n sub-tile
        #pragma unroll 8
        for (int k = 0; k < 64; k++) {
            const ulonglong2 A  = *(const ulonglong2*)&wpT [k*68  + 4*tb];
            const ulonglong2 B0 = *(const ulonglong2*)&bshD[k*128 + 8*tm];
            const ulonglong2 B1 = *(const ulonglong2*)&bshD[k*128 + 8*tm + 4];
            acc[0][0]=ffma2(A.x,B0.x,acc[0][0]); acc[0][1]=ffma2(A.x,B0.y,acc[0][1]);
            acc[0][2]=ffma2(A.x,B1.x,acc[0][2]); acc[0][3]=ffma2(A.x,B1.y,acc[0][3]);
            acc[1][0]=ffma2(A.y,B0.x,acc[1][0]); acc[1][1]=ffma2(A.y,B0.y,acc[1][1]);
            acc[1][2]=ffma2(A.y,B1.x,acc[1][2]); acc[1][3]=ffma2(A.y,B1.y,acc[1][3]);
        }
        __syncthreads();
    }

    // write split-K partials
    const size_t base = ((size_t)r*ECHUNK + chunk) * (Bz*Mv);
    #pragma unroll
    for (int p = 0; p < 2; p++) {
        float lo[4], hi[4];
        #pragma unroll
        for (int j = 0; j < 4; j++) unpack2(acc[p][j], lo[j], hi[j]);
        *(float4*)&g_epart[base + (size_t)(4*tb + 2*p    )*Mv + 4*tm]
            = make_float4(lo[0], lo[1], lo[2], lo[3]);
        *(float4*)&g_epart[base + (size_t)(4*tb + 2*p + 1)*Mv + 4*tm]
            = make_float4(hi[0], hi[1], hi[2], hi[3]);
    }
    // reduce pow partial sum for this (r, chunk)
    red[t] = psum; __syncthreads();
    for (int off = 128; off; off >>= 1) { if (t < off) red[t] += red[t+off]; __syncthreads(); }
    if (t == 0) g_tpartR[r*ECHUNK + chunk] = red[0];
}

// ----- kernel 6: reduce split-K + apply 1/(total_r+eps) + transpose --------
__global__ void reduce_out_kernel(float* __restrict__ out)
{
    const int gid = blockIdx.x*256 + threadIdx.x;   // 0..R*B*M-1
    const int r = gid >> 12;
    const int b = (gid >> 6) & 63;
    const int m = gid & 63;
    const float inv = 1.f / (g_totals[1 + r] + 1e-5f);
    float s = 0.f;
    for (int c = 0; c < ECHUNK; c++)
        s += g_epart[(((size_t)r*ECHUNK + c)*Bz + b)*Mv + m];
    out[(size_t)b*(Rv*Mv) + r*Mv + m] = s * inv;
}

// ---------------------------------------------------------------------------
extern "C" void kernel_launch(void* const* d_in, const int* in_sizes, int n_in,
                              void* d_out, int out_size)
{
    const float* h_t     = (const float*)d_in[0];
    const float* ww      = (const float*)d_in[1];
    const float* wr      = (const float*)d_in[2];
    const float* memory  = (const float*)d_in[3];
    const float* key_w   = (const float*)d_in[4];
    const float* key_b   = (const float*)d_in[5];
    const float* beta_w  = (const float*)d_in[6];
    const float* beta_b  = (const float*)d_in[7];
    const float* gate_w  = (const float*)d_in[8];
    const float* gate_b  = (const float*)d_in[9];
    const float* shift_w = (const float*)d_in[10];
    const float* shift_b = (const float*)d_in[11];
    const float* gamma_w = (const float*)d_in[12];
    const float* gamma_b = (const float*)d_in[13];
    const float* erase_w = (const float*)d_in[14];
    const float* erase_b = (const float*)d_in[15];
    const float* add_w   = (const float*)d_in[16];
    const float* add_b   = (const float*)d_in[17];
    const int*   bank    = (const int*)d_in[18];
    float* out = (float*)d_out;

    const int MEMUP_SMEM = (4096 + 8192 + 8192) * 4;               // 81920 B
    const int FUSED_SMEM = (8192 + 4352 + 4288 + 384 + 256) * 4;   // 69888 B
    cudaFuncSetAttribute(memupdate_kernel,
        cudaFuncAttributeMaxDynamicSharedMemorySize, MEMUP_SMEM);
    cudaFuncSetAttribute(fused_read_kernel,
        cudaFuncAttributeMaxDynamicSharedMemorySize, FUSED_SMEM);

    // head params (shared by all 5 weight updates)
    heads_kernel<<<Bz, 256>>>(h_t, key_w, key_b, beta_w, beta_b, gate_w, gate_b,
                              shift_w, shift_b, gamma_w, gamma_b,
                              erase_w, erase_b, add_w, add_b);

    // --- write head: content addressing on m0 ---
    sim_kernel<<<SIMBLK, 256>>>(memory, bank, 0);
    reduce_sumexp_kernel<<<Bz, 256>>>();
    csp_write_kernel<<<dim3(CSPBLK, Bz), 256>>>(ww);
    reduce_totalW_kernel<<<1, 256>>>();

    // --- memory erase/add ---
    memupdate_kernel<<<NNv/64, 256, MEMUP_SMEM>>>(memory, bank);

    // --- read heads: shared content addressing on m1, fused csp+einsum ---
    sim_kernel<<<SIMBLK, 256>>>(memory, bank, 1);
    reduce_sumexp_kernel<<<Bz, 256>>>();
    fused_read_kernel<<<dim3(ECHUNK, Rv), 256, FUSED_SMEM>>>(wr);
    reduce_totalR_kernel<<<Rv, 256>>>();

    // --- final: reduce split-K, normalize, transpose ---
    reduce_out_kernel<<<(Rv*Bz*Mv)/256, 256>>>(out);
}